// round 15
// baseline (speedup 1.0000x reference)
#include <cuda_runtime.h>
#include <cuda_fp16.h>
#include <cstdint>
#include <cstddef>

// Problem dims
#define BB    64
#define CC    512
#define HWS   784
#define MTOT  (BB * HWS)        // 50176
#define MTILE 128
#define NTILE 128
#define KCH   64
#define NCHNK (CC / KCH)        // 8

// smem: A half-K persistent [256k][256B] = 65536 | B 2 stages x 16384 = 32768
//       params at 98304: 5*128 f32 = 2560, rb 512 f32 = 2048 -> total 102912 (2 CTAs/SM)
// epilogue D tile 128x129 f32 = 66048 reuses A region (+512B of B stage 0)
#define SM_BOFF  65536u
#define BSTG     16384u
#define SMPAR    98304u
#define SMTOTAL  102912u
#define TPITCH   129

// ---------------- scratch ----------------
__device__ __half g_wb[CC * CC];            // sign(W) [N][K], +-1 fp16
__device__ float g_alpha[CC];
__device__ float g_beta2[CC];

// ---------------- helpers ----------------
static __device__ __forceinline__ uint32_t smem_u32(const void* p) {
    uint32_t a;
    asm("{ .reg .u64 t; cvta.to.shared.u64 t, %1; cvt.u32.u64 %0, t; }" : "=r"(a) : "l"(p));
    return a;
}
static __device__ __forceinline__ void cp16(uint32_t s, const void* g) {
    asm volatile("cp.async.cg.shared.global [%0], [%1], 16;" :: "r"(s), "l"(g) : "memory");
}
#define CP_COMMIT() asm volatile("cp.async.commit_group;" ::: "memory")
#define CP_WAIT(n)  asm volatile("cp.async.wait_group %0;" :: "n"(n) : "memory")

static __device__ __forceinline__ void ldsm4(uint32_t* r, uint32_t a) {
    asm volatile("ldmatrix.sync.aligned.m8n8.x4.shared.b16 {%0,%1,%2,%3}, [%4];"
                 : "=r"(r[0]), "=r"(r[1]), "=r"(r[2]), "=r"(r[3]) : "r"(a));
}
static __device__ __forceinline__ void ldsm4t(uint32_t* r, uint32_t a) {
    asm volatile("ldmatrix.sync.aligned.m8n8.x4.trans.shared.b16 {%0,%1,%2,%3}, [%4];"
                 : "=r"(r[0]), "=r"(r[1]), "=r"(r[2]), "=r"(r[3]) : "r"(a));
}
static __device__ __forceinline__ void sts128(uint32_t a, uint32_t x0, uint32_t x1,
                                              uint32_t x2, uint32_t x3) {
    asm volatile("st.shared.v4.b32 [%0], {%1,%2,%3,%4};"
                 :: "r"(a), "r"(x0), "r"(x1), "r"(x2), "r"(x3) : "memory");
}
static __device__ __forceinline__ void mma_h(uint32_t* c, const uint32_t* a,
                                             uint32_t b0, uint32_t b1) {
    asm volatile(
        "mma.sync.aligned.m16n8k16.row.col.f16.f16.f16.f16 "
        "{%0,%1}, {%2,%3,%4,%5}, {%6,%7}, {%0,%1};"
        : "+r"(c[0]), "+r"(c[1])
        : "r"(a[0]), "r"(a[1]), "r"(a[2]), "r"(a[3]), "r"(b0), "r"(b1));
}
static __device__ __forceinline__ uint32_t swzB(int row, int seg) {
    return (uint32_t)(row * 128 + ((seg ^ (row & 7)) << 4));
}
static __device__ __forceinline__ uint32_t sgnh2(float a, float b) {
    return ((a >= 0.f) ? 0x3C00u : 0xBC00u) | (((b >= 0.f) ? 0x3C00u : 0xBC00u) << 16);
}
static __device__ __forceinline__ uint32_t pack2(float a, float b) {
    uint32_t ua = __float_as_uint(a), ub = __float_as_uint(b);
    return 0x3C003C00u | ((ua >> 16) & 0x8000u) | (ub & 0x80000000u);
}
static __device__ __forceinline__ float4 ldg4c(const float* p0, const float* p1,
                                               int cross, int off) {
    if (off + 4 <= cross) return *reinterpret_cast<const float4*>(p0 + off);
    if (off >= cross)     return *reinterpret_cast<const float4*>(p1 + off);
    float4 v;
    v.x = (off     >= cross ? p1 : p0)[off];
    v.y = (off + 1 >= cross ? p1 : p0)[off + 1];
    v.z = (off + 2 >= cross ? p1 : p0)[off + 2];
    v.w = (off + 3 >= cross ? p1 : p0)[off + 3];
    return v;
}

// ---------------- kernel 1: epilogue constants + sign(W) fp16 ----------------
__global__ void prep_kernel(const float* __restrict__ W, const float* __restrict__ gam,
                            const float* __restrict__ bet, const float* __restrict__ mea,
                            const float* __restrict__ var) {
    int wid = threadIdx.x >> 5, lane = threadIdx.x & 31;
    int o = blockIdx.x * 8 + wid;
    const float4* wr = reinterpret_cast<const float4*>(W + (size_t)o * CC + lane * 16);
    float s = 0.f;
    uint32_t h[8];
    #pragma unroll
    for (int j = 0; j < 4; j++) {
        float4 v = wr[j];
        s += fabsf(v.x) + fabsf(v.y) + fabsf(v.z) + fabsf(v.w);
        h[2 * j]     = sgnh2(v.x, v.y);
        h[2 * j + 1] = sgnh2(v.z, v.w);
    }
    uint4* dst = reinterpret_cast<uint4*>(g_wb + (size_t)o * CC + lane * 16);
    dst[0] = make_uint4(h[0], h[1], h[2], h[3]);
    dst[1] = make_uint4(h[4], h[5], h[6], h[7]);
    #pragma unroll
    for (int off = 16; off > 0; off >>= 1) s += __shfl_xor_sync(0xffffffffu, s, off);
    if (lane == 0) {
        float scale = s * (1.0f / 512.0f);
        float A = gam[o] * rsqrtf(var[o] + 1e-5f);
        g_alpha[o] = A * scale;
        g_beta2[o] = bet[o] - A * mea[o];
    }
}

// ---------------- kernel 2: fused binarize (half-K persistent) + fp16 mma GEMM ----------------
__global__ void __launch_bounds__(256, 2)
gemm_kernel(const float* __restrict__ x, const float* __restrict__ rb,
            const float* __restrict__ slope, const float* __restrict__ shift,
            const float* __restrict__ pbias, float* __restrict__ out)
{
    extern __shared__ char smem[];
    const uint32_t sb = smem_u32(smem);
    const int tid = threadIdx.x, wid = tid >> 5, lane = tid & 31;
    const int m0 = blockIdx.y * MTILE;
    const int n0 = blockIdx.x * NTILE;

    float* alphaS = reinterpret_cast<float*>(smem + SMPAR);
    float* betaS  = alphaS + 128;
    float* slopeS = alphaS + 256;
    float* shiftS = alphaS + 384;
    float* pbiasS = alphaS + 512;
    float* rbS    = alphaS + 640;    // 512 entries
    if (tid < 128) {
        alphaS[tid] = g_alpha[n0 + tid];
        betaS[tid]  = g_beta2[n0 + tid];
        slopeS[tid] = slope[n0 + tid];
        shiftS[tid] = shift[n0 + tid];
        pbiasS[tid] = pbias[n0 + tid];
    }
    rbS[tid]       = rb[tid];        // own-thread use only (k = half*256 + tid)
    rbS[tid + 256] = rb[tid + 256];

    // ---- B loader (cp.async): 128 rows x 8 segs = 1024 cp16, 4 per thread ----
    auto loadB = [&](int c, int st) {
        const uint32_t so = sb + SM_BOFF + (uint32_t)st * BSTG;
        const char* gb = (const char*)g_wb + ((size_t)n0 * CC + c * KCH) * 2;
        #pragma unroll
        for (int j = 0; j < 4; j++) {
            int u = tid + j * 256;
            int row = u >> 3, seg = u & 7;
            cp16(so + swzB(row, seg), gb + (size_t)row * (CC * 2) + seg * 16);
        }
        CP_COMMIT();
    };

    // ---- A binarizer: one half (256 k) of A into smem [k][m], 256B rows ----
    const int b0  = m0 / HWS;
    const int hw0 = m0 - b0 * HWS;
    const int cross = HWS - hw0;
    auto binA = [&](int half) {
        const int k = half * 256 + tid;              // this thread's channel
        const float* p0 = x + ((size_t)b0 * CC + k) * HWS + hw0;
        const float* p1 = p0 + (size_t)CC * HWS - HWS;
        const float rbv = rbS[k];                    // own write
        const uint32_t ab = sb + (uint32_t)tid * 256u;   // local k-row = tid
        #pragma unroll 4
        for (int j = 0; j < 16; j++) {
            float4 v0 = ldg4c(p0, p1, cross, j * 8);
            float4 v1 = ldg4c(p0, p1, cross, j * 8 + 4);
            sts128(ab + ((uint32_t)(j ^ (tid & 7)) << 4),
                   pack2(v0.x + rbv, v0.y + rbv), pack2(v0.z + rbv, v0.w + rbv),
                   pack2(v1.x + rbv, v1.y + rbv), pack2(v1.z + rbv, v1.w + rbv));
        }
    };

    loadB(0, 0);                      // B(0) in flight during the A prologue
    binA(0);
    __syncthreads();                  // A half 0 + params visible

    // ---- mainloop ----
    uint32_t acc[4][4][2] = {};       // warp 64m x 32n
    const int mw = (wid >> 2) * 64;
    const int nw = (wid & 3) * 32;
    const int aKl   = (lane & 7) + ((lane >> 4) & 1) * 8;
    const int aMsel = (lane >> 3) & 1;
    const int bRowSel = (lane & 7) + ((lane >> 3) & 1) * 8;
    const int bSegHi  = (lane >> 4) & 1;

    uint32_t af[2][4][4], bf[2][2][4];
    auto ldsm_step = [&](int c, uint32_t bBase, int ks, int buf) {
        const int row = (c & 3) * KCH + ks * 16 + aKl;    // local row 0..255
        const uint32_t rbase = sb + (uint32_t)row * 256u;
        #pragma unroll
        for (int mt = 0; mt < 4; mt++) {
            int mseg = ((mw + mt * 16) >> 3) + aMsel;
            ldsm4t(af[buf][mt], rbase + ((uint32_t)(mseg ^ (row & 7)) << 4));
        }
        #pragma unroll
        for (int nb = 0; nb < 2; nb++)
            ldsm4(bf[buf][nb], bBase + swzB(nw + nb * 16 + bRowSel, ks * 2 + bSegHi));
    };
    auto mma_step = [&](int buf) {
        #pragma unroll
        for (int mt = 0; mt < 4; mt++) {
            #pragma unroll
            for (int nt = 0; nt < 4; nt++)
                mma_h(acc[mt][nt], af[buf][mt],
                      bf[buf][nt >> 1][nt & 1], bf[buf][nt >> 1][(nt & 1) + 2]);
        }
    };

    #pragma unroll 1
    for (int c = 0; c < NCHNK; c++) {
        CP_WAIT(0);                   // B(c) resident
        __syncthreads();              // + all reads of B stage (c+1)&1 and (c==4) A half 0 done
        if (c + 1 < NCHNK) loadB(c + 1, (c + 1) & 1);
        if (c == 4) { binA(1); __syncthreads(); }     // switch to A half 1

        const uint32_t bBase = sb + SM_BOFF + (uint32_t)(c & 1) * BSTG;
        ldsm_step(c, bBase, 0, 0);
        #pragma unroll
        for (int ks = 0; ks < 4; ks++) {
            const int cur = ks & 1;
            if (ks < 3) ldsm_step(c, bBase, ks + 1, cur ^ 1);
            mma_step(cur);
        }
    }

    // ---- stage D through smem (reuses A region) ----
    float* tile = reinterpret_cast<float*>(smem);
    __syncthreads();
    const int dr = lane >> 2;
    const int dc = (lane & 3) * 2;
    #pragma unroll
    for (int mt = 0; mt < 4; mt++) {
        #pragma unroll
        for (int nt = 0; nt < 4; nt++) {
            int r = mw + mt * 16 + dr;
            int c2 = nw + nt * 8 + dc;
            float2 lo = __half22float2(*reinterpret_cast<__half2*>(&acc[mt][nt][0]));
            float2 hi = __half22float2(*reinterpret_cast<__half2*>(&acc[mt][nt][1]));
            tile[r * TPITCH + c2]           = lo.x;
            tile[r * TPITCH + c2 + 1]       = lo.y;
            tile[(r + 8) * TPITCH + c2]     = hi.x;
            tile[(r + 8) * TPITCH + c2 + 1] = hi.y;
        }
    }
    __syncthreads();

    // ---- epilogue: BN + residual + RPReLU ----
    #pragma unroll 4
    for (int g = 0; g < 16; g++) {
        const int nl = wid + 8 * g;
        const int n = n0 + nl;
        const float al = alphaS[nl], be = betaS[nl];
        const float sl = slopeS[nl], sh = shiftS[nl], pb = pbiasS[nl];
        #pragma unroll
        for (int j = 0; j < 4; j++) {
            int ml = lane + 32 * j;
            int m = m0 + ml;
            int b = m / HWS;
            int hw = m - b * HWS;
            size_t gi = ((size_t)(b * CC + n)) * HWS + hw;
            float raw = tile[ml * TPITCH + nl];
            float sv = fmaf(al, raw, be) + x[gi];
            float t = sv - sh;
            out[gi] = ((t > 0.f) ? t : sl * t) + pb;
        }
    }
}

// ---------------- launch ----------------
extern "C" void kernel_launch(void* const* d_in, const int* in_sizes, int n_in,
                              void* d_out, int out_size) {
    const float* x   = (const float*)d_in[0];
    const float* rb  = (const float*)d_in[1];
    const float* W   = (const float*)d_in[2];
    const float* gam = (const float*)d_in[3];
    const float* bet = (const float*)d_in[4];
    const float* mea = (const float*)d_in[5];
    const float* var = (const float*)d_in[6];
    const float* slo = (const float*)d_in[7];
    const float* shi = (const float*)d_in[8];
    const float* pbi = (const float*)d_in[9];
    float* out = (float*)d_out;

    cudaFuncSetAttribute(gemm_kernel, cudaFuncAttributeMaxDynamicSharedMemorySize, SMTOTAL);

    prep_kernel<<<64, 256>>>(W, gam, bet, mea, var);
    gemm_kernel<<<dim3(4, MTOT / MTILE), 256, SMTOTAL>>>(x, rb, slo, shi, pbi, out);
}

// round 16
// speedup vs baseline: 1.8567x; 1.8567x over previous
#include <cuda_runtime.h>
#include <cuda_fp16.h>
#include <cstdint>
#include <cstddef>

// Problem dims
#define BB    64
#define CC    512
#define HWS   784
#define MTOT  (BB * HWS)        // 50176
#define MTILE 128
#define NTILE 128
#define KCH   64                // K chunk (fp16 -> 128B rows)
#define NCHNK (CC / KCH)        // 8

// smem: 3 stages x { A[128][128B] 16384 + B[128][128B] 16384 } = 98304
// params at 98304: 5 x 128 f32 = 2560 -> total 100864  (2 CTAs/SM)
// epilogue D tile 128 x 129 f32 = 66048 reuses stage area
#define ASZ      16384u
#define STAGEB   32768u
#define SMPAR    98304u
#define SMTOTAL  100864u
#define TPITCH   129

// ---------------- scratch ----------------
__device__ __half g_a[(size_t)MTOT * CC];   // binarized activations [M][K], +-1 fp16
__device__ __half g_wb[CC * CC];            // sign(W) [N][K], +-1 fp16
__device__ float g_alpha[CC];
__device__ float g_beta2[CC];

// ---------------- helpers ----------------
static __device__ __forceinline__ uint32_t smem_u32(const void* p) {
    uint32_t a;
    asm("{ .reg .u64 t; cvta.to.shared.u64 t, %1; cvt.u32.u64 %0, t; }" : "=r"(a) : "l"(p));
    return a;
}
static __device__ __forceinline__ void cp16(uint32_t s, const void* g) {
    asm volatile("cp.async.cg.shared.global [%0], [%1], 16;" :: "r"(s), "l"(g) : "memory");
}
#define CP_COMMIT() asm volatile("cp.async.commit_group;" ::: "memory")
#define CP_WAIT(n)  asm volatile("cp.async.wait_group %0;" :: "n"(n) : "memory")

static __device__ __forceinline__ void ldsm4(uint32_t* r, uint32_t a) {
    asm volatile("ldmatrix.sync.aligned.m8n8.x4.shared.b16 {%0,%1,%2,%3}, [%4];"
                 : "=r"(r[0]), "=r"(r[1]), "=r"(r[2]), "=r"(r[3]) : "r"(a));
}
static __device__ __forceinline__ void mma_h(uint32_t* c, const uint32_t* a,
                                             uint32_t b0, uint32_t b1) {
    asm volatile(
        "mma.sync.aligned.m16n8k16.row.col.f16.f16.f16.f16 "
        "{%0,%1}, {%2,%3,%4,%5}, {%6,%7}, {%0,%1};"
        : "+r"(c[0]), "+r"(c[1])
        : "r"(a[0]), "r"(a[1]), "r"(a[2]), "r"(a[3]), "r"(b0), "r"(b1));
}
static __device__ __forceinline__ uint32_t swzB(int row, int seg) {
    return (uint32_t)(row * 128 + ((seg ^ (row & 7)) << 4));
}
static __device__ __forceinline__ uint32_t sgnh2(float a, float b) {
    return ((a >= 0.f) ? 0x3C00u : 0xBC00u) | (((b >= 0.f) ? 0x3C00u : 0xBC00u) << 16);
}

// ---------------- kernel 1: prep (blocks 0..63) + binarize (blocks 64+) ----------------
// prep: per-output-channel alpha/beta + sign(W) fp16 (reads W only)
// binarize: x + rsign_bias -> sign -> g_a [M][K] fp16 (reads x only)
__global__ void pre_kernel(const float* __restrict__ W, const float* __restrict__ gam,
                           const float* __restrict__ bet, const float* __restrict__ mea,
                           const float* __restrict__ var,
                           const float* __restrict__ x, const float* __restrict__ rb) {
    __shared__ unsigned short ts[64][72];   // used by binarize role only
    const int tid = threadIdx.x;

    if (blockIdx.x < 64) {
        // ---------- prep role ----------
        int wid = tid >> 5, lane = tid & 31;
        int o = blockIdx.x * 8 + wid;
        const float4* wr = reinterpret_cast<const float4*>(W + (size_t)o * CC + lane * 16);
        float s = 0.f;
        uint32_t h[8];
        #pragma unroll
        for (int j = 0; j < 4; j++) {
            float4 v = wr[j];
            s += fabsf(v.x) + fabsf(v.y) + fabsf(v.z) + fabsf(v.w);
            h[2 * j]     = sgnh2(v.x, v.y);
            h[2 * j + 1] = sgnh2(v.z, v.w);
        }
        uint4* dst = reinterpret_cast<uint4*>(g_wb + (size_t)o * CC + lane * 16);
        dst[0] = make_uint4(h[0], h[1], h[2], h[3]);
        dst[1] = make_uint4(h[4], h[5], h[6], h[7]);
        #pragma unroll
        for (int off = 16; off > 0; off >>= 1) s += __shfl_xor_sync(0xffffffffu, s, off);
        if (lane == 0) {
            float scale = s * (1.0f / 512.0f);
            float A = gam[o] * rsqrtf(var[o] + 1e-5f);
            g_alpha[o] = A * scale;
            g_beta2[o] = bet[o] - A * mea[o];
        }
        return;
    }

    // ---------- binarize role ----------
    const int bid = blockIdx.x - 64;        // 0..6655 = 13 * 8 * 64
    const int hwg = bid % 13;
    const int kg  = (bid / 13) % 8;
    const int b   = bid / 104;
    const int k0  = kg * 64;
    const int hw0 = hwg * 64;

    #pragma unroll
    for (int i = 0; i < 4; i++) {
        int idx = tid + i * 256;
        int cc = idx >> 4;
        int hs = idx & 15;
        int hw = hw0 + hs * 4;
        float rbv = rb[k0 + cc];
        const float* xp = x + (size_t)((b << 9) + k0 + cc) * HWS + hw;
        if (hw + 3 < HWS) {
            float4 v = *reinterpret_cast<const float4*>(xp);
            ts[hs * 4 + 0][cc] = (v.x + rbv >= 0.f) ? 0x3C00 : 0xBC00;
            ts[hs * 4 + 1][cc] = (v.y + rbv >= 0.f) ? 0x3C00 : 0xBC00;
            ts[hs * 4 + 2][cc] = (v.z + rbv >= 0.f) ? 0x3C00 : 0xBC00;
            ts[hs * 4 + 3][cc] = (v.w + rbv >= 0.f) ? 0x3C00 : 0xBC00;
        } else {
            #pragma unroll
            for (int e = 0; e < 4; e++)
                if (hw + e < HWS)
                    ts[hs * 4 + e][cc] = (xp[e] + rbv >= 0.f) ? 0x3C00 : 0xBC00;
        }
    }
    __syncthreads();
    #pragma unroll
    for (int i = 0; i < 2; i++) {
        int idx = tid + i * 256;
        int row = idx >> 3;
        int seg = idx & 7;
        int hw = hw0 + row;
        if (hw < HWS) {
            uint4 v = *reinterpret_cast<const uint4*>(&ts[row][seg * 8]);
            *reinterpret_cast<uint4*>(
                &g_a[(size_t)(b * HWS + hw) * CC + k0 + seg * 8]) = v;
        }
    }
}

// ---------------- kernel 2: fp16 mma GEMM (3-stage, frag double-buffer) ----------------
__global__ void __launch_bounds__(256, 2)
gemm_kernel(const float* __restrict__ x, const float* __restrict__ slope,
            const float* __restrict__ shift, const float* __restrict__ pbias,
            float* __restrict__ out)
{
    extern __shared__ char smem[];
    const uint32_t sb = smem_u32(smem);
    const int tid = threadIdx.x, wid = tid >> 5, lane = tid & 31;
    const int m0 = blockIdx.y * MTILE;
    const int n0 = blockIdx.x * NTILE;

    float* alphaS = reinterpret_cast<float*>(smem + SMPAR);
    float* betaS  = alphaS + 128;
    float* slopeS = alphaS + 256;
    float* shiftS = alphaS + 384;
    float* pbiasS = alphaS + 512;
    if (tid < 128) {
        alphaS[tid] = g_alpha[n0 + tid];
        betaS[tid]  = g_beta2[n0 + tid];
        slopeS[tid] = slope[n0 + tid];
        shiftS[tid] = shift[n0 + tid];
        pbiasS[tid] = pbias[n0 + tid];
    }

    const int ldrow = tid >> 3;           // 0..31
    const int ldseg = tid & 7;
    auto load_stage = [&](int c, int st) {
        const uint32_t so = sb + (uint32_t)st * STAGEB;
        const char* ga = (const char*)g_a  + ((size_t)m0 * CC + c * KCH) * 2;
        const char* gb = (const char*)g_wb + ((size_t)n0 * CC + c * KCH) * 2;
        #pragma unroll
        for (int j = 0; j < 4; j++) {
            int row = ldrow + j * 32;
            cp16(so + swzB(row, ldseg), ga + (size_t)row * (CC * 2) + ldseg * 16);
        }
        #pragma unroll
        for (int j = 0; j < 4; j++) {
            int row = ldrow + j * 32;
            cp16(so + ASZ + swzB(row, ldseg), gb + (size_t)row * (CC * 2) + ldseg * 16);
        }
        CP_COMMIT();
    };

    load_stage(0, 0);
    load_stage(1, 1);

    uint32_t acc[4][4][2] = {};           // warp 64m x 32n, f16x2 acc
    const int mw = (wid >> 2) * 64;       // warp row: 0/64
    const int nw = (wid & 3) * 32;        // warp col: 0/32/64/96
    const int rowSel = (lane & 7) + ((lane >> 3) & 1) * 8;
    const int segHi  = (lane >> 4) & 1;

    uint32_t af[2][4][4], bf[2][2][4];
    auto ldsm_step = [&](uint32_t aBase, uint32_t bBase, int ks, int buf) {
        const int kseg = ks * 2 + segHi;
        #pragma unroll
        for (int mt = 0; mt < 4; mt++)
            ldsm4(af[buf][mt], aBase + swzB(mw + mt * 16 + rowSel, kseg));
        #pragma unroll
        for (int nb = 0; nb < 2; nb++)
            ldsm4(bf[buf][nb], bBase + swzB(nw + nb * 16 + rowSel, kseg));
    };
    auto mma_step = [&](int buf) {
        #pragma unroll
        for (int mt = 0; mt < 4; mt++) {
            #pragma unroll
            for (int nt = 0; nt < 4; nt++)
                mma_h(acc[mt][nt], af[buf][mt],
                      bf[buf][nt >> 1][nt & 1], bf[buf][nt >> 1][(nt & 1) + 2]);
        }
    };

    #pragma unroll
    for (int c = 0; c < NCHNK; c++) {
        if (c < NCHNK - 1) { CP_WAIT(1); } else { CP_WAIT(0); }
        __syncthreads();
        if (c + 2 < NCHNK) load_stage(c + 2, (c + 2) % 3);

        const uint32_t aBase = sb + (uint32_t)(c % 3) * STAGEB;
        const uint32_t bBase = aBase + ASZ;

        ldsm_step(aBase, bBase, 0, 0);
        #pragma unroll
        for (int ks = 0; ks < 4; ks++) {
            const int cur = ks & 1;
            if (ks < 3) ldsm_step(aBase, bBase, ks + 1, cur ^ 1);
            mma_step(cur);
        }
    }

    // ---- stage D through smem ----
    float* tile = reinterpret_cast<float*>(smem);
    __syncthreads();                       // stages dead; safe to reuse
    const int dr = lane >> 2;
    const int dc = (lane & 3) * 2;
    #pragma unroll
    for (int mt = 0; mt < 4; mt++) {
        #pragma unroll
        for (int nt = 0; nt < 4; nt++) {
            int r = mw + mt * 16 + dr;
            int c2 = nw + nt * 8 + dc;
            float2 lo = __half22float2(*reinterpret_cast<__half2*>(&acc[mt][nt][0]));
            float2 hi = __half22float2(*reinterpret_cast<__half2*>(&acc[mt][nt][1]));
            tile[r * TPITCH + c2]           = lo.x;
            tile[r * TPITCH + c2 + 1]       = lo.y;
            tile[(r + 8) * TPITCH + c2]     = hi.x;
            tile[(r + 8) * TPITCH + c2 + 1] = hi.y;
        }
    }
    __syncthreads();

    // ---- epilogue: BN + residual + RPReLU, coalesced over hw ----
    #pragma unroll 4
    for (int g = 0; g < 16; g++) {
        const int nl = wid + 8 * g;
        const int n = n0 + nl;
        const float al = alphaS[nl], be = betaS[nl];
        const float sl = slopeS[nl], sh = shiftS[nl], pb = pbiasS[nl];
        #pragma unroll
        for (int j = 0; j < 4; j++) {
            int ml = lane + 32 * j;
            int m = m0 + ml;
            int b = m / HWS;
            int hw = m - b * HWS;
            size_t gi = ((size_t)(b * CC + n)) * HWS + hw;
            float raw = tile[ml * TPITCH + nl];
            float sv = fmaf(al, raw, be) + x[gi];
            float t = sv - sh;
            out[gi] = ((t > 0.f) ? t : sl * t) + pb;
        }
    }
}

// ---------------- launch ----------------
extern "C" void kernel_launch(void* const* d_in, const int* in_sizes, int n_in,
                              void* d_out, int out_size) {
    const float* x   = (const float*)d_in[0];
    const float* rb  = (const float*)d_in[1];
    const float* W   = (const float*)d_in[2];
    const float* gam = (const float*)d_in[3];
    const float* bet = (const float*)d_in[4];
    const float* mea = (const float*)d_in[5];
    const float* var = (const float*)d_in[6];
    const float* slo = (const float*)d_in[7];
    const float* shi = (const float*)d_in[8];
    const float* pbi = (const float*)d_in[9];
    float* out = (float*)d_out;

    cudaFuncSetAttribute(gemm_kernel, cudaFuncAttributeMaxDynamicSharedMemorySize, SMTOTAL);

    pre_kernel<<<64 + 13 * 8 * 64, 256>>>(W, gam, bet, mea, var, x, rb);
    gemm_kernel<<<dim3(4, MTOT / MTILE), 256, SMTOTAL>>>(x, slo, shi, pbi, out);
}